// round 15
// baseline (speedup 1.0000x reference)
#include <cuda_runtime.h>
#include <cuda_bf16.h>
#include <cuda_fp16.h>
#include <cstdint>

#define N_NODES 50000
#define N_EDGES 800000
#define TOT_E   (N_EDGES + N_NODES)   // edges + self loops
#define NEG_SLOPE 0.2f
#define FULL 0xffffffffu

#define SCAN_CHUNK 512
#define NB_SCAN ((N_NODES + SCAN_CHUNK - 1) / SCAN_CHUNK)   // 98

// tensor GEMM smem geometry (bf16 elements)
#define ASTRIDE 72     // 64 k + 8 pad
#define BSTRIDE 136    // 128 n + 8 pad
#define KCH 64
#define SM_AHI 0
#define SM_ALO (128 * ASTRIDE)
#define SM_BHI (2 * 128 * ASTRIDE)
#define SM_BLO (2 * 128 * ASTRIDE + KCH * BSTRIDE)
#define SMEM_ELEMS (2 * 128 * ASTRIDE + 2 * KCH * BSTRIDE)   // 35840
#define SMEM_BYTES (SMEM_ELEMS * 2)                           // 71680

// ---------------- scratch (static device globals; no allocation) ----------------
__device__ __half         g_h16[N_NODES * 128];   // x @ W, fp16 (gather payload)
__device__ unsigned short g_xhi[N_NODES * 128];   // layer output, bf16 hi plane
__device__ unsigned short g_xlo[N_NODES * 128];   // layer output, bf16 lo plane
__device__ float  g_as[N_NODES * 4];
__device__ float  g_ad[N_NODES * 4];
__device__ int    g_cnt   [N_NODES];
__device__ int    g_rowptr[N_NODES + 1];
__device__ int    g_cursor[N_NODES];
__device__ int    g_srcs  [TOT_E];
__device__ int    g_bsum  [NB_SCAN];
__device__ int    g_offs  [NB_SCAN];
__device__ int    g_is64;

// ---------------- edge_index dtype detection (1 warp) ----------------
__global__ void detect_kernel(const int* __restrict__ ei32, int* __restrict__ flag) {
    int lane = threadIdx.x;
    int nz = 0;
#pragma unroll
    for (int i = lane; i < 128; i += 32) nz |= ei32[2 * i + 1];
    int any = __any_sync(FULL, nz != 0);
    if (lane == 0) *flag = any ? 0 : 1;
}

__device__ __forceinline__ int load_idx(const void* ei, int is64, long long pos) {
    if (is64) return (int)((const long long*)ei)[pos];
    return ((const int*)ei)[pos];
}

// ---------------- CSR build ----------------
__global__ void hist_kernel(const void* __restrict__ ei, const int* __restrict__ flag,
                            int* __restrict__ cnt) {
    int i = blockIdx.x * blockDim.x + threadIdx.x;
    if (i >= TOT_E) return;
    int is64 = *flag;
    int d = (i < N_EDGES) ? load_idx(ei, is64, (long long)N_EDGES + i) : (i - N_EDGES);
    atomicAdd(&cnt[d], 1);
}

__global__ __launch_bounds__(256) void block_reduce_kernel(const int* __restrict__ cnt,
                                                           int* __restrict__ bsum) {
    int b = blockIdx.x, tid = threadIdx.x;
    int i0 = b * SCAN_CHUNK + tid * 2;
    int v = 0;
    if (i0 < N_NODES)     v += cnt[i0];
    if (i0 + 1 < N_NODES) v += cnt[i0 + 1];
#pragma unroll
    for (int off = 16; off; off >>= 1) v += __shfl_xor_sync(FULL, v, off);
    __shared__ int ws[8];
    int lane = tid & 31, wid = tid >> 5;
    if (lane == 0) ws[wid] = v;
    __syncthreads();
    if (tid == 0) {
        int s = 0;
#pragma unroll
        for (int w = 0; w < 8; w++) s += ws[w];
        bsum[b] = s;
    }
}

__global__ void scan_partials_kernel(const int* __restrict__ bsum,
                                     int* __restrict__ offs, int* __restrict__ rowptr) {
    __shared__ int sh[128];
    int tid = threadIdx.x;
    int v = (tid < NB_SCAN) ? bsum[tid] : 0;
    sh[tid] = v;
    __syncthreads();
#pragma unroll
    for (int off = 1; off < 128; off <<= 1) {
        int y = (tid >= off) ? sh[tid - off] : 0;
        __syncthreads();
        sh[tid] += y;
        __syncthreads();
    }
    if (tid < NB_SCAN) offs[tid] = sh[tid] - v;
    if (tid == 127) rowptr[N_NODES] = sh[127];
}

__global__ __launch_bounds__(256) void chunk_scan_kernel(const int* __restrict__ cnt,
                                                         const int* __restrict__ offs,
                                                         int* __restrict__ rowptr,
                                                         int* __restrict__ cursor) {
    int b = blockIdx.x, tid = threadIdx.x;
    int lane = tid & 31, wid = tid >> 5;
    int i0 = b * SCAN_CHUNK + tid * 2;
    int v0 = (i0 < N_NODES) ? cnt[i0] : 0;
    int v1 = (i0 + 1 < N_NODES) ? cnt[i0 + 1] : 0;
    int t = v0 + v1;
    int x = t;
#pragma unroll
    for (int off = 1; off < 32; off <<= 1) {
        int y = __shfl_up_sync(FULL, x, off);
        if (lane >= off) x += y;
    }
    __shared__ int ws[8], wpre[8];
    if (lane == 31) ws[wid] = x;
    __syncthreads();
    if (tid == 0) {
        int run = 0;
#pragma unroll
        for (int w = 0; w < 8; w++) { wpre[w] = run; run += ws[w]; }
    }
    __syncthreads();
    int excl = x - t + wpre[wid] + offs[b];
    if (i0 < N_NODES)     { rowptr[i0] = excl;          cursor[i0] = excl; }
    if (i0 + 1 < N_NODES) { rowptr[i0 + 1] = excl + v0; cursor[i0 + 1] = excl + v0; }
}

__global__ void scatter_kernel(const void* __restrict__ ei, const int* __restrict__ flag,
                               int* __restrict__ cursor, int* __restrict__ srcs) {
    int i = blockIdx.x * blockDim.x + threadIdx.x;
    if (i >= TOT_E) return;
    int is64 = *flag;
    int s, d;
    if (i < N_EDGES) {
        s = load_idx(ei, is64, i);
        d = load_idx(ei, is64, (long long)N_EDGES + i);
    } else { s = i - N_EDGES; d = s; }
    int pos = atomicAdd(&cursor[d], 1);
    srcs[pos] = s;
}

// ---------------- tensor-core helpers ----------------
__device__ __forceinline__ uint32_t smem_u32(const void* p) {
    return (uint32_t)__cvta_generic_to_shared(p);
}
__device__ __forceinline__ void ldm_x4(uint32_t* r, uint32_t addr) {
    asm volatile("ldmatrix.sync.aligned.m8n8.x4.shared.b16 {%0,%1,%2,%3}, [%4];"
        : "=r"(r[0]), "=r"(r[1]), "=r"(r[2]), "=r"(r[3]) : "r"(addr));
}
__device__ __forceinline__ void ldm_x2t(uint32_t* r, uint32_t addr) {
    asm volatile("ldmatrix.sync.aligned.m8n8.x2.trans.shared.b16 {%0,%1}, [%2];"
        : "=r"(r[0]), "=r"(r[1]) : "r"(addr));
}
__device__ __forceinline__ void mma_bf16(float* c, const uint32_t* a, const uint32_t* b) {
    asm volatile("mma.sync.aligned.m16n8k16.row.col.f32.bf16.bf16.f32 "
        "{%0,%1,%2,%3}, {%4,%5,%6,%7}, {%8,%9}, {%0,%1,%2,%3};"
        : "+f"(c[0]), "+f"(c[1]), "+f"(c[2]), "+f"(c[3])
        : "r"(a[0]), "r"(a[1]), "r"(a[2]), "r"(a[3]), "r"(b[0]), "r"(b[1]));
}
__device__ __forceinline__ void split2(float a, float b, uint32_t& hi, uint32_t& lo) {
    __nv_bfloat16 ah = __float2bfloat16_rn(a);
    __nv_bfloat16 bh = __float2bfloat16_rn(b);
    __nv_bfloat16 al = __float2bfloat16_rn(a - __bfloat162float(ah));
    __nv_bfloat16 bl = __float2bfloat16_rn(b - __bfloat162float(bh));
    hi = ((uint32_t)__bfloat16_as_ushort(bh) << 16) | (uint32_t)__bfloat16_as_ushort(ah);
    lo = ((uint32_t)__bfloat16_as_ushort(bl) << 16) | (uint32_t)__bfloat16_as_ushort(al);
}

// ---------------- fused tensor GEMM + alpha (h stored fp16) ----------------
// SPLIT_IN: activations arrive pre-split as bf16 hi/lo planes (no cvt math).
template <int H, bool SPLIT_IN>
__global__ __launch_bounds__(512) void gemm_tc_kernel(
    const float* __restrict__ xf,
    const unsigned short* __restrict__ xhi, const unsigned short* __restrict__ xlo,
    const float* __restrict__ W,
    const float* __restrict__ a_s, const float* __restrict__ a_d,
    __half* __restrict__ out, float* __restrict__ out_s, float* __restrict__ out_d,
    int nrows) {
    extern __shared__ __align__(16) unsigned short sm[];
    unsigned short* Ahi = sm + SM_AHI;
    unsigned short* Alo = sm + SM_ALO;
    unsigned short* Bhi = sm + SM_BHI;
    unsigned short* Blo = sm + SM_BLO;

    int tid = threadIdx.x;
    int w = tid >> 5, lane = tid & 31;
    int warpRow = w >> 2, warpCol = w & 3;
    int rowBase = blockIdx.x * 128;

    float c[2][4][4];
#pragma unroll
    for (int mt = 0; mt < 2; mt++)
#pragma unroll
        for (int nt = 0; nt < 4; nt++)
#pragma unroll
            for (int f = 0; f < 4; f++) c[mt][nt][f] = 0.f;

    for (int ch = 0; ch < 2; ch++) {
        // A chunk: 128 rows x 64 k
#pragma unroll
        for (int i = 0; i < 4; i++) {
            int r = tid >> 2;
            int c4 = (tid & 3) * 4 + i;            // 0..15 (4-element granules)
            int grow = rowBase + r;
            int base = r * ASTRIDE + c4 * 4;
            if (SPLIT_IN) {
                uint2 hv = make_uint2(0u, 0u), lv = make_uint2(0u, 0u);
                if (grow < nrows) {
                    size_t off = (size_t)grow * 128 + ch * KCH + c4 * 4;
                    hv = *(const uint2*)(xhi + off);
                    lv = *(const uint2*)(xlo + off);
                }
                *(uint2*)(Ahi + base) = hv;
                *(uint2*)(Alo + base) = lv;
            } else {
                float4 v = make_float4(0.f, 0.f, 0.f, 0.f);
                if (grow < nrows)
                    v = *(const float4*)(xf + (size_t)grow * 128 + ch * KCH + c4 * 4);
                uint32_t h0, l0, h1, l1;
                split2(v.x, v.y, h0, l0);
                split2(v.z, v.w, h1, l1);
                *(uint32_t*)(Ahi + base)     = h0;
                *(uint32_t*)(Ahi + base + 2) = h1;
                *(uint32_t*)(Alo + base)     = l0;
                *(uint32_t*)(Alo + base + 2) = l1;
            }
        }
        // W chunk: 64 k rows x 128 n (always split from fp32; small)
#pragma unroll
        for (int i = 0; i < 4; i++) {
            int kr = tid >> 3;
            int c4 = (tid & 7) * 4 + i;
            float4 v = *(const float4*)(W + (size_t)(ch * KCH + kr) * 128 + c4 * 4);
            uint32_t h0, l0, h1, l1;
            split2(v.x, v.y, h0, l0);
            split2(v.z, v.w, h1, l1);
            int base = kr * BSTRIDE + c4 * 4;
            *(uint32_t*)(Bhi + base)     = h0;
            *(uint32_t*)(Bhi + base + 2) = h1;
            *(uint32_t*)(Blo + base)     = l0;
            *(uint32_t*)(Blo + base + 2) = l1;
        }
        __syncthreads();

#pragma unroll
        for (int ks = 0; ks < 4; ks++) {
            int k0 = ks * 16;
            uint32_t ah[2][4], al[2][4], bh[4][2], bl[4][2];
#pragma unroll
            for (int mt = 0; mt < 2; mt++) {
                int idx = (warpRow * 32 + mt * 16 + (lane & 15)) * ASTRIDE
                        + k0 + ((lane >> 4) << 3);
                ldm_x4(ah[mt], smem_u32(Ahi + idx));
                ldm_x4(al[mt], smem_u32(Alo + idx));
            }
#pragma unroll
            for (int nt = 0; nt < 4; nt++) {
                int idx = (k0 + (lane & 15)) * BSTRIDE + warpCol * 32 + nt * 8;
                ldm_x2t(bh[nt], smem_u32(Bhi + idx));
                ldm_x2t(bl[nt], smem_u32(Blo + idx));
            }
#pragma unroll
            for (int mt = 0; mt < 2; mt++)
#pragma unroll
                for (int nt = 0; nt < 4; nt++) {
                    mma_bf16(c[mt][nt], ah[mt], bh[nt]);
                    mma_bf16(c[mt][nt], ah[mt], bl[nt]);
                    mma_bf16(c[mt][nt], al[mt], bh[nt]);
                }
        }
        __syncthreads();
    }

    // ---- epilogue: store h as fp16 ----
#pragma unroll
    for (int mt = 0; mt < 2; mt++) {
#pragma unroll
        for (int half = 0; half < 2; half++) {
            int r = rowBase + warpRow * 32 + mt * 16 + (lane >> 2) + half * 8;
            if (r < nrows) {
#pragma unroll
                for (int nt = 0; nt < 4; nt++) {
                    int col = warpCol * 32 + nt * 8 + 2 * (lane & 3);
                    __half2 hv = __floats2half2_rn(c[mt][nt][half * 2],
                                                   c[mt][nt][half * 2 + 1]);
                    *(__half2*)(out + (size_t)r * 128 + col) = hv;
                }
            }
        }
    }

    // ---- fused alpha: per-row dots from fp32 accumulators ----
    float asv[4][2], adv[4][2];
#pragma unroll
    for (int nt = 0; nt < 4; nt++) {
        int col = warpCol * 32 + nt * 8 + 2 * (lane & 3);
        asv[nt][0] = a_s[col]; asv[nt][1] = a_s[col + 1];
        adv[nt][0] = a_d[col]; adv[nt][1] = a_d[col + 1];
    }
    float* redAS = (float*)sm;          // overlay (safe after final sync)
    float* redAD = redAS + 4 * 128;

#pragma unroll
    for (int mt = 0; mt < 2; mt++) {
#pragma unroll
        for (int half = 0; half < 2; half++) {
            float ps = 0.f, pd = 0.f;
#pragma unroll
            for (int nt = 0; nt < 4; nt++) {
                ps += c[mt][nt][half * 2] * asv[nt][0] + c[mt][nt][half * 2 + 1] * asv[nt][1];
                pd += c[mt][nt][half * 2] * adv[nt][0] + c[mt][nt][half * 2 + 1] * adv[nt][1];
            }
            ps += __shfl_xor_sync(FULL, ps, 1); ps += __shfl_xor_sync(FULL, ps, 2);
            pd += __shfl_xor_sync(FULL, pd, 1); pd += __shfl_xor_sync(FULL, pd, 2);
            int lrow = warpRow * 32 + mt * 16 + (lane >> 2) + half * 8;
            int r = rowBase + lrow;
            if ((lane & 3) == 0) {
                if (H == 4) {
                    if (r < nrows) {
                        out_s[r * 4 + warpCol] = ps;
                        out_d[r * 4 + warpCol] = pd;
                    }
                } else {
                    redAS[warpCol * 128 + lrow] = ps;
                    redAD[warpCol * 128 + lrow] = pd;
                }
            }
        }
    }
    if (H == 1) {
        __syncthreads();
        if (tid < 128) {
            int r = rowBase + tid;
            if (r < nrows) {
                float s = redAS[tid] + redAS[128 + tid] + redAS[256 + tid] + redAS[384 + tid];
                float d = redAD[tid] + redAD[128 + tid] + redAD[256 + tid] + redAD[384 + tid];
                out_s[r] = s;
                out_d[r] = d;
            }
        }
    }
}

// ---------------- softmax + aggregation: warp per dst node (fp16 gather) ------
// SPLIT_OUT: emit result as bf16 hi/lo planes for the next layer's GEMM.
template <int H, bool SPLIT_OUT>
__global__ __launch_bounds__(256) void aggregate_kernel(const __half* __restrict__ h,
                                                        const float* __restrict__ as_,
                                                        const float* __restrict__ ad_,
                                                        const int* __restrict__ rowptr,
                                                        const int* __restrict__ srcs,
                                                        const float* __restrict__ bias,
                                                        float* __restrict__ outf,
                                                        unsigned short* __restrict__ ohi,
                                                        unsigned short* __restrict__ olo) {
    __shared__ float s_w[8][32 * H];
    __shared__ int   s_s[8][32];
    int n = (blockIdx.x * blockDim.x + threadIdx.x) >> 5;
    if (n >= N_NODES) return;
    int w8 = threadIdx.x >> 5;
    int lane = threadIdx.x & 31;
    int start = rowptr[n], end = rowptr[n + 1];
    int deg = end - start;
    constexpr int LPH = 32 / H;
    int head = (H == 1) ? 0 : (lane / LPH);

    float ad_all[H];
#pragma unroll
    for (int hh = 0; hh < H; hh++) ad_all[hh] = ad_[n * H + hh];

    // ---- Phase A ----
    float m[H], p[H], e_lane[H];
    int s_lane = 0;
#pragma unroll
    for (int hh = 0; hh < H; hh++) { m[hh] = -1e30f; p[hh] = 0.f; e_lane[hh] = -1e30f; }

    if (lane < deg) {
        s_lane = srcs[start + lane];
        if (H == 4) {
            float4 a4 = *(const float4*)(as_ + (size_t)s_lane * 4);
            float ea[4] = {a4.x, a4.y, a4.z, a4.w};
#pragma unroll
            for (int hh = 0; hh < 4; hh++) {
                float e = ea[hh] + ad_all[hh];
                e = (e > 0.f) ? e : NEG_SLOPE * e;
                e_lane[hh] = e; m[hh] = e; p[hh] = 1.f;
            }
        } else {
            float e = as_[s_lane] + ad_all[0];
            e = (e > 0.f) ? e : NEG_SLOPE * e;
            e_lane[0] = e; m[0] = e; p[0] = 1.f;
        }
    }
    for (int k = start + 32 + lane; k < end; k += 32) {
        int s = srcs[k];
#pragma unroll
        for (int hh = 0; hh < H; hh++) {
            float e = as_[(size_t)s * H + hh] + ad_all[hh];
            e = (e > 0.f) ? e : NEG_SLOPE * e;
            if (e > m[hh]) { p[hh] = p[hh] * __expf(m[hh] - e) + 1.f; m[hh] = e; }
            else           { p[hh] += __expf(e - m[hh]); }
        }
    }
#pragma unroll
    for (int hh = 0; hh < H; hh++) {
        float mm = m[hh], pp = p[hh];
#pragma unroll
        for (int off = 16; off > 0; off >>= 1) {
            float mo = __shfl_xor_sync(FULL, mm, off);
            float po = __shfl_xor_sync(FULL, pp, off);
            float mn = fmaxf(mm, mo);
            pp = pp * __expf(mm - mn) + po * __expf(mo - mn);
            mm = mn;
        }
        m[hh] = mm; p[hh] = pp;
    }
    {
        float wv[H];
#pragma unroll
        for (int hh = 0; hh < H; hh++)
            wv[hh] = __expf(e_lane[hh] - m[hh]) / p[hh];
        if (H == 4) {
            *(float4*)&s_w[w8][lane * 4] = make_float4(wv[0], wv[1], wv[2], wv[3]);
        } else {
            s_w[w8][lane] = wv[0];
        }
        s_s[w8][lane] = s_lane;
    }
    __syncwarp();

    // ---- Phase B: fp16 gather, fp32 accumulate ----
    float4 acc = make_float4(0.f, 0.f, 0.f, 0.f);
    int cached = (deg < 32) ? deg : 32;
#pragma unroll 4
    for (int kk = 0; kk < cached; kk++) {
        int s = s_s[w8][kk];
        float wgt = s_w[w8][kk * H + head];
        uint2 u = *(const uint2*)(h + (size_t)s * 128 + lane * 4);
        float2 f01 = __half22float2(*(__half2*)&u.x);
        float2 f23 = __half22float2(*(__half2*)&u.y);
        acc.x += f01.x * wgt; acc.y += f01.y * wgt;
        acc.z += f23.x * wgt; acc.w += f23.y * wgt;
    }
    if (deg > 32) {
        float mh, invh, adh;
        if (H == 1) { mh = m[0]; invh = 1.f / p[0]; adh = ad_all[0]; }
        else {
            mh   = (head == 0) ? m[0] : (head == 1) ? m[1] : (head == 2) ? m[2] : m[3];
            float ph = (head == 0) ? p[0] : (head == 1) ? p[1] : (head == 2) ? p[2] : p[3];
            invh = 1.f / ph;
            adh  = (head == 0) ? ad_all[0] : (head == 1) ? ad_all[1]
                 : (head == 2) ? ad_all[2] : ad_all[3];
        }
        for (int k = start + 32; k < end; k++) {
            int s = srcs[k];
            float e = as_[(size_t)s * H + head] + adh;
            e = (e > 0.f) ? e : NEG_SLOPE * e;
            float wgt = __expf(e - mh) * invh;
            uint2 u = *(const uint2*)(h + (size_t)s * 128 + lane * 4);
            float2 f01 = __half22float2(*(__half2*)&u.x);
            float2 f23 = __half22float2(*(__half2*)&u.y);
            acc.x += f01.x * wgt; acc.y += f01.y * wgt;
            acc.z += f23.x * wgt; acc.w += f23.y * wgt;
        }
    }
    float4 bv = *(const float4*)(bias + lane * 4);
    float r0 = fmaxf(acc.x + bv.x, 0.f);
    float r1 = fmaxf(acc.y + bv.y, 0.f);
    float r2 = fmaxf(acc.z + bv.z, 0.f);
    float r3 = fmaxf(acc.w + bv.w, 0.f);
    if (SPLIT_OUT) {
        uint32_t h01, l01, h23, l23;
        split2(r0, r1, h01, l01);
        split2(r2, r3, h23, l23);
        size_t off = (size_t)n * 128 + lane * 4;
        *(uint2*)(ohi + off) = make_uint2(h01, h23);
        *(uint2*)(olo + off) = make_uint2(l01, l23);
    } else {
        *(float4*)(outf + (size_t)n * 128 + lane * 4) = make_float4(r0, r1, r2, r3);
    }
}

// ---------------- launcher ----------------
extern "C" void kernel_launch(void* const* d_in, const int* in_sizes, int n_in,
                              void* d_out, int out_size) {
    const float* x  = (const float*)d_in[0];
    const void*  ei = d_in[1];
    const float* W0 = (const float*)d_in[2];
    const float* as0 = (const float*)d_in[3];
    const float* ad0 = (const float*)d_in[4];
    const float* b0 = (const float*)d_in[5];
    const float* W1 = (const float*)d_in[6];
    const float* as1 = (const float*)d_in[7];
    const float* ad1 = (const float*)d_in[8];
    const float* b1 = (const float*)d_in[9];
    const float* W2 = (const float*)d_in[10];
    const float* as2 = (const float*)d_in[11];
    const float* ad2 = (const float*)d_in[12];
    const float* b2 = (const float*)d_in[13];
    float* out = (float*)d_out;

    void* p;
    cudaGetSymbolAddress(&p, g_h16);    __half* hbuf  = (__half*)p;
    cudaGetSymbolAddress(&p, g_xhi);    unsigned short* xhi = (unsigned short*)p;
    cudaGetSymbolAddress(&p, g_xlo);    unsigned short* xlo = (unsigned short*)p;
    cudaGetSymbolAddress(&p, g_as);     float* asbuf  = (float*)p;
    cudaGetSymbolAddress(&p, g_ad);     float* adbuf  = (float*)p;
    cudaGetSymbolAddress(&p, g_cnt);    int*   cnt    = (int*)p;
    cudaGetSymbolAddress(&p, g_rowptr); int*   rowptr = (int*)p;
    cudaGetSymbolAddress(&p, g_cursor); int*   cursor = (int*)p;
    cudaGetSymbolAddress(&p, g_srcs);   int*   srcs   = (int*)p;
    cudaGetSymbolAddress(&p, g_bsum);   int*   bsum   = (int*)p;
    cudaGetSymbolAddress(&p, g_offs);   int*   offs   = (int*)p;
    cudaGetSymbolAddress(&p, g_is64);   int*   flag   = (int*)p;

    cudaFuncSetAttribute(gemm_tc_kernel<4, false>,
                         cudaFuncAttributeMaxDynamicSharedMemorySize, SMEM_BYTES);
    cudaFuncSetAttribute(gemm_tc_kernel<4, true>,
                         cudaFuncAttributeMaxDynamicSharedMemorySize, SMEM_BYTES);
    cudaFuncSetAttribute(gemm_tc_kernel<1, true>,
                         cudaFuncAttributeMaxDynamicSharedMemorySize, SMEM_BYTES);

    const int grid_e  = (TOT_E + 255) / 256;
    const int grid_w  = (N_NODES * 32 + 255) / 256;   // warp per node
    const int grid_g  = (N_NODES + 127) / 128;        // GEMM row tiles

    // CSR build, with layer-0 GEMM slotted into the middle (it has no CSR
    // dependency) so the ncu -s 5 window catches the GEMM, not a scan kernel.
    detect_kernel       <<<1, 32>>>((const int*)ei, flag);
    cudaMemsetAsync(cnt, 0, N_NODES * sizeof(int));
    hist_kernel         <<<grid_e, 256>>>(ei, flag, cnt);
    block_reduce_kernel <<<NB_SCAN, 256>>>(cnt, bsum);
    gemm_tc_kernel<4, false><<<grid_g, 512, SMEM_BYTES>>>(x, nullptr, nullptr, W0,
                                                          as0, ad0, hbuf, asbuf, adbuf,
                                                          N_NODES);
    scan_partials_kernel<<<1, 128>>>(bsum, offs, rowptr);
    chunk_scan_kernel   <<<NB_SCAN, 256>>>(cnt, offs, rowptr, cursor);
    scatter_kernel      <<<grid_e, 256>>>(ei, flag, cursor, srcs);

    // layer 0 aggregate (H=4) -> split bf16 planes
    aggregate_kernel<4, true><<<grid_w, 256>>>(hbuf, asbuf, adbuf, rowptr, srcs, b0,
                                               nullptr, xhi, xlo);
    // layer 1 (H=4), split-in, split-out
    gemm_tc_kernel<4, true><<<grid_g, 512, SMEM_BYTES>>>(nullptr, xhi, xlo, W1,
                                                         as1, ad1, hbuf, asbuf, adbuf,
                                                         N_NODES);
    aggregate_kernel<4, true><<<grid_w, 256>>>(hbuf, asbuf, adbuf, rowptr, srcs, b1,
                                               nullptr, xhi, xlo);
    // layer 2 (H=1), split-in, fp32 out
    gemm_tc_kernel<1, true><<<grid_g, 512, SMEM_BYTES>>>(nullptr, xhi, xlo, W2,
                                                         as2, ad2, hbuf, asbuf, adbuf,
                                                         N_NODES);
    aggregate_kernel<1, false><<<grid_w, 256>>>(hbuf, asbuf, adbuf, rowptr, srcs, b2,
                                                out, nullptr, nullptr);
}

// round 16
// speedup vs baseline: 1.0317x; 1.0317x over previous
#include <cuda_runtime.h>
#include <cuda_bf16.h>
#include <cuda_fp16.h>
#include <cstdint>

#define N_NODES 50000
#define N_EDGES 800000
#define TOT_E   (N_EDGES + N_NODES)   // edges + self loops
#define NEG_SLOPE 0.2f
#define FULL 0xffffffffu

#define SCAN_CHUNK 512
#define NB_SCAN ((N_NODES + SCAN_CHUNK - 1) / SCAN_CHUNK)   // 98

// tensor GEMM smem geometry: full K=128 resident, bf16 hi/lo planes
#define STRIDE 136                       // 128 + 8 pad (shorts)
#define SA_HI 0
#define SA_LO (128 * STRIDE)             // 17408
#define SB_HI (2 * 128 * STRIDE)         // 34816
#define SB_LO (3 * 128 * STRIDE)         // 52224
#define GEMM_SM_SHORTS (4 * 128 * STRIDE)     // 69632
#define GEMM_SM_BYTES  (GEMM_SM_SHORTS * 2)   // 139264

// ---------------- scratch (static device globals; no allocation) ----------------
__device__ __half         g_h16[N_NODES * 128];   // x @ W, fp16 (gather payload)
__device__ unsigned short g_xhi[N_NODES * 128];   // activations, bf16 hi plane
__device__ unsigned short g_xlo[N_NODES * 128];   // activations, bf16 lo plane
__device__ unsigned short g_whi[3 * 128 * 128];   // weights, bf16 hi planes
__device__ unsigned short g_wlo[3 * 128 * 128];   // weights, bf16 lo planes
__device__ float  g_as[N_NODES * 4];
__device__ float  g_ad[N_NODES * 4];
__device__ int    g_cnt   [N_NODES];
__device__ int    g_rowptr[N_NODES + 1];
__device__ int    g_cursor[N_NODES];
__device__ int    g_srcs  [TOT_E];
__device__ int    g_bsum  [NB_SCAN];
__device__ int    g_offs  [NB_SCAN];
__device__ int    g_is64;

// ---------------- edge_index dtype detection (1 warp) ----------------
__global__ void detect_kernel(const int* __restrict__ ei32, int* __restrict__ flag) {
    int lane = threadIdx.x;
    int nz = 0;
#pragma unroll
    for (int i = lane; i < 128; i += 32) nz |= ei32[2 * i + 1];
    int any = __any_sync(FULL, nz != 0);
    if (lane == 0) *flag = any ? 0 : 1;
}

__device__ __forceinline__ int load_idx(const void* ei, int is64, long long pos) {
    if (is64) return (int)((const long long*)ei)[pos];
    return ((const int*)ei)[pos];
}

// ---------------- CSR build ----------------
__global__ void hist_kernel(const void* __restrict__ ei, const int* __restrict__ flag,
                            int* __restrict__ cnt) {
    int i = blockIdx.x * blockDim.x + threadIdx.x;
    if (i >= TOT_E) return;
    int is64 = *flag;
    int d = (i < N_EDGES) ? load_idx(ei, is64, (long long)N_EDGES + i) : (i - N_EDGES);
    atomicAdd(&cnt[d], 1);
}

__global__ __launch_bounds__(256) void block_reduce_kernel(const int* __restrict__ cnt,
                                                           int* __restrict__ bsum) {
    int b = blockIdx.x, tid = threadIdx.x;
    int i0 = b * SCAN_CHUNK + tid * 2;
    int v = 0;
    if (i0 < N_NODES)     v += cnt[i0];
    if (i0 + 1 < N_NODES) v += cnt[i0 + 1];
#pragma unroll
    for (int off = 16; off; off >>= 1) v += __shfl_xor_sync(FULL, v, off);
    __shared__ int ws[8];
    int lane = tid & 31, wid = tid >> 5;
    if (lane == 0) ws[wid] = v;
    __syncthreads();
    if (tid == 0) {
        int s = 0;
#pragma unroll
        for (int w = 0; w < 8; w++) s += ws[w];
        bsum[b] = s;
    }
}

__global__ void scan_partials_kernel(const int* __restrict__ bsum,
                                     int* __restrict__ offs, int* __restrict__ rowptr) {
    __shared__ int sh[128];
    int tid = threadIdx.x;
    int v = (tid < NB_SCAN) ? bsum[tid] : 0;
    sh[tid] = v;
    __syncthreads();
#pragma unroll
    for (int off = 1; off < 128; off <<= 1) {
        int y = (tid >= off) ? sh[tid - off] : 0;
        __syncthreads();
        sh[tid] += y;
        __syncthreads();
    }
    if (tid < NB_SCAN) offs[tid] = sh[tid] - v;
    if (tid == 127) rowptr[N_NODES] = sh[127];
}

__global__ __launch_bounds__(256) void chunk_scan_kernel(const int* __restrict__ cnt,
                                                         const int* __restrict__ offs,
                                                         int* __restrict__ rowptr,
                                                         int* __restrict__ cursor) {
    int b = blockIdx.x, tid = threadIdx.x;
    int lane = tid & 31, wid = tid >> 5;
    int i0 = b * SCAN_CHUNK + tid * 2;
    int v0 = (i0 < N_NODES) ? cnt[i0] : 0;
    int v1 = (i0 + 1 < N_NODES) ? cnt[i0 + 1] : 0;
    int t = v0 + v1;
    int x = t;
#pragma unroll
    for (int off = 1; off < 32; off <<= 1) {
        int y = __shfl_up_sync(FULL, x, off);
        if (lane >= off) x += y;
    }
    __shared__ int ws[8], wpre[8];
    if (lane == 31) ws[wid] = x;
    __syncthreads();
    if (tid == 0) {
        int run = 0;
#pragma unroll
        for (int w = 0; w < 8; w++) { wpre[w] = run; run += ws[w]; }
    }
    __syncthreads();
    int excl = x - t + wpre[wid] + offs[b];
    if (i0 < N_NODES)     { rowptr[i0] = excl;          cursor[i0] = excl; }
    if (i0 + 1 < N_NODES) { rowptr[i0 + 1] = excl + v0; cursor[i0 + 1] = excl + v0; }
}

__global__ void scatter_kernel(const void* __restrict__ ei, const int* __restrict__ flag,
                               int* __restrict__ cursor, int* __restrict__ srcs) {
    int i = blockIdx.x * blockDim.x + threadIdx.x;
    if (i >= TOT_E) return;
    int is64 = *flag;
    int s, d;
    if (i < N_EDGES) {
        s = load_idx(ei, is64, i);
        d = load_idx(ei, is64, (long long)N_EDGES + i);
    } else { s = i - N_EDGES; d = s; }
    int pos = atomicAdd(&cursor[d], 1);
    srcs[pos] = s;
}

// ---------------- tensor-core / async helpers ----------------
__device__ __forceinline__ uint32_t smem_u32(const void* p) {
    return (uint32_t)__cvta_generic_to_shared(p);
}
__device__ __forceinline__ void cp16(uint32_t dst, const void* src, int szbytes) {
    asm volatile("cp.async.cg.shared.global [%0], [%1], 16, %2;"
        :: "r"(dst), "l"(src), "r"(szbytes));
}
__device__ __forceinline__ void ldm_x4(uint32_t* r, uint32_t addr) {
    asm volatile("ldmatrix.sync.aligned.m8n8.x4.shared.b16 {%0,%1,%2,%3}, [%4];"
        : "=r"(r[0]), "=r"(r[1]), "=r"(r[2]), "=r"(r[3]) : "r"(addr));
}
__device__ __forceinline__ void ldm_x2t(uint32_t* r, uint32_t addr) {
    asm volatile("ldmatrix.sync.aligned.m8n8.x2.trans.shared.b16 {%0,%1}, [%2];"
        : "=r"(r[0]), "=r"(r[1]) : "r"(addr));
}
__device__ __forceinline__ void mma_bf16(float* c, const uint32_t* a, const uint32_t* b) {
    asm volatile("mma.sync.aligned.m16n8k16.row.col.f32.bf16.bf16.f32 "
        "{%0,%1,%2,%3}, {%4,%5,%6,%7}, {%8,%9}, {%0,%1,%2,%3};"
        : "+f"(c[0]), "+f"(c[1]), "+f"(c[2]), "+f"(c[3])
        : "r"(a[0]), "r"(a[1]), "r"(a[2]), "r"(a[3]), "r"(b[0]), "r"(b[1]));
}
__device__ __forceinline__ void split2(float a, float b, uint32_t& hi, uint32_t& lo) {
    __nv_bfloat16 ah = __float2bfloat16_rn(a);
    __nv_bfloat16 bh = __float2bfloat16_rn(b);
    __nv_bfloat16 al = __float2bfloat16_rn(a - __bfloat162float(ah));
    __nv_bfloat16 bl = __float2bfloat16_rn(b - __bfloat162float(bh));
    hi = ((uint32_t)__bfloat16_as_ushort(bh) << 16) | (uint32_t)__bfloat16_as_ushort(ah);
    lo = ((uint32_t)__bfloat16_as_ushort(bl) << 16) | (uint32_t)__bfloat16_as_ushort(al);
}

// ---------------- fp32 -> bf16 hi/lo plane split (x and W) ----------------
__global__ void split_kernel(const float* __restrict__ src,
                             unsigned short* __restrict__ hi,
                             unsigned short* __restrict__ lo, int n4) {
    int i = blockIdx.x * blockDim.x + threadIdx.x;
    if (i >= n4) return;
    float4 v = ((const float4*)src)[i];
    uint32_t h0, l0, h1, l1;
    split2(v.x, v.y, h0, l0);
    split2(v.z, v.w, h1, l1);
    ((uint2*)hi)[i] = make_uint2(h0, h1);
    ((uint2*)lo)[i] = make_uint2(l0, l1);
}

// ---------------- fused tensor GEMM + alpha (all operands pre-split) ----------
// Full-K smem residency, cp.async front-loaded, ONE sync, 8 straight k-steps.
template <int H>
__global__ __launch_bounds__(512) void gemm_tc_kernel(
    const unsigned short* __restrict__ xhi, const unsigned short* __restrict__ xlo,
    const unsigned short* __restrict__ whi, const unsigned short* __restrict__ wlo,
    const float* __restrict__ a_s, const float* __restrict__ a_d,
    __half* __restrict__ out, float* __restrict__ out_s, float* __restrict__ out_d,
    int nrows) {
    extern __shared__ __align__(16) unsigned short sm[];
    unsigned short* Ahi = sm + SA_HI;
    unsigned short* Alo = sm + SA_LO;
    unsigned short* Bhi = sm + SB_HI;
    unsigned short* Blo = sm + SB_LO;

    int tid = threadIdx.x;
    int w = tid >> 5, lane = tid & 31;
    int warpRow = w >> 2, warpCol = w & 3;
    int rowBase = blockIdx.x * 128;

    // ---- front-load everything via cp.async (2048 16B segs per plane) ----
#pragma unroll
    for (int i = 0; i < 4; i++) {
        int seg = tid + i * 512;
        int r = seg >> 4, s = seg & 15;
        int grow = rowBase + r;
        int sz = (grow < nrows) ? 16 : 0;
        const unsigned short* srch = (grow < nrows) ? xhi + (size_t)grow * 128 + s * 8 : xhi;
        const unsigned short* srcl = (grow < nrows) ? xlo + (size_t)grow * 128 + s * 8 : xlo;
        int so = r * STRIDE + s * 8;
        cp16(smem_u32(Ahi + so), srch, sz);
        cp16(smem_u32(Alo + so), srcl, sz);
    }
#pragma unroll
    for (int i = 0; i < 4; i++) {
        int seg = tid + i * 512;
        int kr = seg >> 4, s = seg & 15;
        size_t go = (size_t)kr * 128 + s * 8;
        int so = kr * STRIDE + s * 8;
        cp16(smem_u32(Bhi + so), whi + go, 16);
        cp16(smem_u32(Blo + so), wlo + go, 16);
    }
    asm volatile("cp.async.commit_group;");

    float c[2][4][4];
#pragma unroll
    for (int mt = 0; mt < 2; mt++)
#pragma unroll
        for (int nt = 0; nt < 4; nt++)
#pragma unroll
            for (int f = 0; f < 4; f++) c[mt][nt][f] = 0.f;

    asm volatile("cp.async.wait_group 0;");
    __syncthreads();

    // ---- 8 uninterrupted k-steps ----
#pragma unroll
    for (int ks = 0; ks < 8; ks++) {
        int k0 = ks * 16;
        uint32_t ah[2][4], al[2][4], bh[4][2], bl[4][2];
#pragma unroll
        for (int mt = 0; mt < 2; mt++) {
            int idx = (warpRow * 32 + mt * 16 + (lane & 15)) * STRIDE
                    + k0 + ((lane >> 4) << 3);
            ldm_x4(ah[mt], smem_u32(Ahi + idx));
            ldm_x4(al[mt], smem_u32(Alo + idx));
        }
#pragma unroll
        for (int nt = 0; nt < 4; nt++) {
            int idx = (k0 + (lane & 15)) * STRIDE + warpCol * 32 + nt * 8;
            ldm_x2t(bh[nt], smem_u32(Bhi + idx));
            ldm_x2t(bl[nt], smem_u32(Blo + idx));
        }
#pragma unroll
        for (int mt = 0; mt < 2; mt++)
#pragma unroll
            for (int nt = 0; nt < 4; nt++) {
                mma_bf16(c[mt][nt], ah[mt], bh[nt]);
                mma_bf16(c[mt][nt], ah[mt], bl[nt]);
                mma_bf16(c[mt][nt], al[mt], bh[nt]);
            }
    }

    // ---- epilogue: store h as fp16 ----
#pragma unroll
    for (int mt = 0; mt < 2; mt++) {
#pragma unroll
        for (int half = 0; half < 2; half++) {
            int r = rowBase + warpRow * 32 + mt * 16 + (lane >> 2) + half * 8;
            if (r < nrows) {
#pragma unroll
                for (int nt = 0; nt < 4; nt++) {
                    int col = warpCol * 32 + nt * 8 + 2 * (lane & 3);
                    __half2 hv = __floats2half2_rn(c[mt][nt][half * 2],
                                                   c[mt][nt][half * 2 + 1]);
                    *(__half2*)(out + (size_t)r * 128 + col) = hv;
                }
            }
        }
    }

    // ---- fused alpha: per-row dots from fp32 accumulators ----
    float asv[4][2], adv[4][2];
#pragma unroll
    for (int nt = 0; nt < 4; nt++) {
        int col = warpCol * 32 + nt * 8 + 2 * (lane & 3);
        asv[nt][0] = a_s[col]; asv[nt][1] = a_s[col + 1];
        adv[nt][0] = a_d[col]; adv[nt][1] = a_d[col + 1];
    }
    if (H == 1) __syncthreads();       // protect smem overlay below
    float* redAS = (float*)sm;
    float* redAD = redAS + 4 * 128;

#pragma unroll
    for (int mt = 0; mt < 2; mt++) {
#pragma unroll
        for (int half = 0; half < 2; half++) {
            float ps = 0.f, pd = 0.f;
#pragma unroll
            for (int nt = 0; nt < 4; nt++) {
                ps += c[mt][nt][half * 2] * asv[nt][0] + c[mt][nt][half * 2 + 1] * asv[nt][1];
                pd += c[mt][nt][half * 2] * adv[nt][0] + c[mt][nt][half * 2 + 1] * adv[nt][1];
            }
            ps += __shfl_xor_sync(FULL, ps, 1); ps += __shfl_xor_sync(FULL, ps, 2);
            pd += __shfl_xor_sync(FULL, pd, 1); pd += __shfl_xor_sync(FULL, pd, 2);
            int lrow = warpRow * 32 + mt * 16 + (lane >> 2) + half * 8;
            int r = rowBase + lrow;
            if ((lane & 3) == 0) {
                if (H == 4) {
                    if (r < nrows) {
                        out_s[r * 4 + warpCol] = ps;
                        out_d[r * 4 + warpCol] = pd;
                    }
                } else {
                    redAS[warpCol * 128 + lrow] = ps;
                    redAD[warpCol * 128 + lrow] = pd;
                }
            }
        }
    }
    if (H == 1) {
        __syncthreads();
        if (tid < 128) {
            int r = rowBase + tid;
            if (r < nrows) {
                float s = redAS[tid] + redAS[128 + tid] + redAS[256 + tid] + redAS[384 + tid];
                float d = redAD[tid] + redAD[128 + tid] + redAD[256 + tid] + redAD[384 + tid];
                out_s[r] = s;
                out_d[r] = d;
            }
        }
    }
}

// ---------------- softmax + aggregation: warp per dst node (fp16 gather) ------
template <int H, bool SPLIT_OUT>
__global__ __launch_bounds__(256) void aggregate_kernel(const __half* __restrict__ h,
                                                        const float* __restrict__ as_,
                                                        const float* __restrict__ ad_,
                                                        const int* __restrict__ rowptr,
                                                        const int* __restrict__ srcs,
                                                        const float* __restrict__ bias,
                                                        float* __restrict__ outf,
                                                        unsigned short* __restrict__ ohi,
                                                        unsigned short* __restrict__ olo) {
    __shared__ float s_w[8][32 * H];
    __shared__ int   s_s[8][32];
    int n = (blockIdx.x * blockDim.x + threadIdx.x) >> 5;
    if (n >= N_NODES) return;
    int w8 = threadIdx.x >> 5;
    int lane = threadIdx.x & 31;
    int start = rowptr[n], end = rowptr[n + 1];
    int deg = end - start;
    constexpr int LPH = 32 / H;
    int head = (H == 1) ? 0 : (lane / LPH);

    float ad_all[H];
#pragma unroll
    for (int hh = 0; hh < H; hh++) ad_all[hh] = ad_[n * H + hh];

    // ---- Phase A ----
    float m[H], p[H], e_lane[H];
    int s_lane = 0;
#pragma unroll
    for (int hh = 0; hh < H; hh++) { m[hh] = -1e30f; p[hh] = 0.f; e_lane[hh] = -1e30f; }

    if (lane < deg) {
        s_lane = srcs[start + lane];
        if (H == 4) {
            float4 a4 = *(const float4*)(as_ + (size_t)s_lane * 4);
            float ea[4] = {a4.x, a4.y, a4.z, a4.w};
#pragma unroll
            for (int hh = 0; hh < 4; hh++) {
                float e = ea[hh] + ad_all[hh];
                e = (e > 0.f) ? e : NEG_SLOPE * e;
                e_lane[hh] = e; m[hh] = e; p[hh] = 1.f;
            }
        } else {
            float e = as_[s_lane] + ad_all[0];
            e = (e > 0.f) ? e : NEG_SLOPE * e;
            e_lane[0] = e; m[0] = e; p[0] = 1.f;
        }
    }
    for (int k = start + 32 + lane; k < end; k += 32) {
        int s = srcs[k];
#pragma unroll
        for (int hh = 0; hh < H; hh++) {
            float e = as_[(size_t)s * H + hh] + ad_all[hh];
            e = (e > 0.f) ? e : NEG_SLOPE * e;
            if (e > m[hh]) { p[hh] = p[hh] * __expf(m[hh] - e) + 1.f; m[hh] = e; }
            else           { p[hh] += __expf(e - m[hh]); }
        }
    }
#pragma unroll
    for (int hh = 0; hh < H; hh++) {
        float mm = m[hh], pp = p[hh];
#pragma unroll
        for (int off = 16; off > 0; off >>= 1) {
            float mo = __shfl_xor_sync(FULL, mm, off);
            float po = __shfl_xor_sync(FULL, pp, off);
            float mn = fmaxf(mm, mo);
            pp = pp * __expf(mm - mn) + po * __expf(mo - mn);
            mm = mn;
        }
        m[hh] = mm; p[hh] = pp;
    }
    {
        float wv[H];
#pragma unroll
        for (int hh = 0; hh < H; hh++)
            wv[hh] = __expf(e_lane[hh] - m[hh]) / p[hh];
        if (H == 4) {
            *(float4*)&s_w[w8][lane * 4] = make_float4(wv[0], wv[1], wv[2], wv[3]);
        } else {
            s_w[w8][lane] = wv[0];
        }
        s_s[w8][lane] = s_lane;
    }
    __syncwarp();

    // ---- Phase B: fp16 gather, fp32 accumulate ----
    float4 acc = make_float4(0.f, 0.f, 0.f, 0.f);
    int cached = (deg < 32) ? deg : 32;
#pragma unroll 4
    for (int kk = 0; kk < cached; kk++) {
        int s = s_s[w8][kk];
        float wgt = s_w[w8][kk * H + head];
        uint2 u = *(const uint2*)(h + (size_t)s * 128 + lane * 4);
        float2 f01 = __half22float2(*(__half2*)&u.x);
        float2 f23 = __half22float2(*(__half2*)&u.y);
        acc.x += f01.x * wgt; acc.y += f01.y * wgt;
        acc.z += f23.x * wgt; acc.w += f23.y * wgt;
    }
    if (deg > 32) {
        float mh, invh, adh;
        if (H == 1) { mh = m[0]; invh = 1.f / p[0]; adh = ad_all[0]; }
        else {
            mh   = (head == 0) ? m[0] : (head == 1) ? m[1] : (head == 2) ? m[2] : m[3];
            float ph = (head == 0) ? p[0] : (head == 1) ? p[1] : (head == 2) ? p[2] : p[3];
            invh = 1.f / ph;
            adh  = (head == 0) ? ad_all[0] : (head == 1) ? ad_all[1]
                 : (head == 2) ? ad_all[2] : ad_all[3];
        }
        for (int k = start + 32; k < end; k++) {
            int s = srcs[k];
            float e = as_[(size_t)s * H + head] + adh;
            e = (e > 0.f) ? e : NEG_SLOPE * e;
            float wgt = __expf(e - mh) * invh;
            uint2 u = *(const uint2*)(h + (size_t)s * 128 + lane * 4);
            float2 f01 = __half22float2(*(__half2*)&u.x);
            float2 f23 = __half22float2(*(__half2*)&u.y);
            acc.x += f01.x * wgt; acc.y += f01.y * wgt;
            acc.z += f23.x * wgt; acc.w += f23.y * wgt;
        }
    }
    float4 bv = *(const float4*)(bias + lane * 4);
    float r0 = fmaxf(acc.x + bv.x, 0.f);
    float r1 = fmaxf(acc.y + bv.y, 0.f);
    float r2 = fmaxf(acc.z + bv.z, 0.f);
    float r3 = fmaxf(acc.w + bv.w, 0.f);
    if (SPLIT_OUT) {
        uint32_t h01, l01, h23, l23;
        split2(r0, r1, h01, l01);
        split2(r2, r3, h23, l23);
        size_t off = (size_t)n * 128 + lane * 4;
        *(uint2*)(ohi + off) = make_uint2(h01, h23);
        *(uint2*)(olo + off) = make_uint2(l01, l23);
    } else {
        *(float4*)(outf + (size_t)n * 128 + lane * 4) = make_float4(r0, r1, r2, r3);
    }
}

// ---------------- launcher ----------------
extern "C" void kernel_launch(void* const* d_in, const int* in_sizes, int n_in,
                              void* d_out, int out_size) {
    const float* x  = (const float*)d_in[0];
    const void*  ei = d_in[1];
    const float* W0 = (const float*)d_in[2];
    const float* as0 = (const float*)d_in[3];
    const float* ad0 = (const float*)d_in[4];
    const float* b0 = (const float*)d_in[5];
    const float* W1 = (const float*)d_in[6];
    const float* as1 = (const float*)d_in[7];
    const float* ad1 = (const float*)d_in[8];
    const float* b1 = (const float*)d_in[9];
    const float* W2 = (const float*)d_in[10];
    const float* as2 = (const float*)d_in[11];
    const float* ad2 = (const float*)d_in[12];
    const float* b2 = (const float*)d_in[13];
    float* out = (float*)d_out;

    void* p;
    cudaGetSymbolAddress(&p, g_h16);    __half* hbuf  = (__half*)p;
    cudaGetSymbolAddress(&p, g_xhi);    unsigned short* xhi = (unsigned short*)p;
    cudaGetSymbolAddress(&p, g_xlo);    unsigned short* xlo = (unsigned short*)p;
    cudaGetSymbolAddress(&p, g_whi);    unsigned short* whi = (unsigned short*)p;
    cudaGetSymbolAddress(&p, g_wlo);    unsigned short* wlo = (unsigned short*)p;
    cudaGetSymbolAddress(&p, g_as);     float* asbuf  = (float*)p;
    cudaGetSymbolAddress(&p, g_ad);     float* adbuf  = (float*)p;
    cudaGetSymbolAddress(&p, g_cnt);    int*   cnt    = (int*)p;
    cudaGetSymbolAddress(&p, g_rowptr); int*   rowptr = (int*)p;
    cudaGetSymbolAddress(&p, g_cursor); int*   cursor = (int*)p;
    cudaGetSymbolAddress(&p, g_srcs);   int*   srcs   = (int*)p;
    cudaGetSymbolAddress(&p, g_bsum);   int*   bsum   = (int*)p;
    cudaGetSymbolAddress(&p, g_offs);   int*   offs   = (int*)p;
    cudaGetSymbolAddress(&p, g_is64);   int*   flag   = (int*)p;

    cudaFuncSetAttribute(gemm_tc_kernel<4>,
                         cudaFuncAttributeMaxDynamicSharedMemorySize, GEMM_SM_BYTES);
    cudaFuncSetAttribute(gemm_tc_kernel<1>,
                         cudaFuncAttributeMaxDynamicSharedMemorySize, GEMM_SM_BYTES);

    const int grid_e  = (TOT_E + 255) / 256;
    const int grid_w  = (N_NODES * 32 + 255) / 256;   // warp per node
    const int grid_g  = (N_NODES + 127) / 128;        // GEMM row tiles
    const int nx4     = N_NODES * 128 / 4;            // 1.6M float4
    const int nw4     = 128 * 128 / 4;                // 4096 float4 per W

    // presplit + CSR build (layer-0 GEMM slotted for ncu visibility)
    detect_kernel       <<<1, 32>>>((const int*)ei, flag);
    cudaMemsetAsync(cnt, 0, N_NODES * sizeof(int));
    hist_kernel         <<<grid_e, 256>>>(ei, flag, cnt);
    split_kernel        <<<(nx4 + 255) / 256, 256>>>(x, xhi, xlo, nx4);
    split_kernel        <<<(nw4 + 255) / 256, 256>>>(W0, whi,             wlo,             nw4);
    split_kernel        <<<(nw4 + 255) / 256, 256>>>(W1, whi + 128 * 128, wlo + 128 * 128, nw4);
    split_kernel        <<<(nw4 + 255) / 256, 256>>>(W2, whi + 2 * 128 * 128,
                                                         wlo + 2 * 128 * 128, nw4);
    block_reduce_kernel <<<NB_SCAN, 256>>>(cnt, bsum);
    gemm_tc_kernel<4>   <<<grid_g, 512, GEMM_SM_BYTES>>>(xhi, xlo, whi, wlo,
                                                         as0, ad0, hbuf, asbuf, adbuf,
                                                         N_NODES);
    scan_partials_kernel<<<1, 128>>>(bsum, offs, rowptr);
    chunk_scan_kernel   <<<NB_SCAN, 256>>>(cnt, offs, rowptr, cursor);
    scatter_kernel      <<<grid_e, 256>>>(ei, flag, cursor, srcs);

    // layer 0 aggregate (H=4) -> split bf16 planes
    aggregate_kernel<4, true><<<grid_w, 256>>>(hbuf, asbuf, adbuf, rowptr, srcs, b0,
                                               nullptr, xhi, xlo);
    // layer 1 (H=4)
    gemm_tc_kernel<4>   <<<grid_g, 512, GEMM_SM_BYTES>>>(xhi, xlo,
                                                         whi + 128 * 128, wlo + 128 * 128,
                                                         as1, ad1, hbuf, asbuf, adbuf,
                                                         N_NODES);
    aggregate_kernel<4, true><<<grid_w, 256>>>(hbuf, asbuf, adbuf, rowptr, srcs, b1,
                                               nullptr, xhi, xlo);
    // layer 2 (H=1)
    gemm_tc_kernel<1>   <<<grid_g, 512, GEMM_SM_BYTES>>>(xhi, xlo,
                                                         whi + 2 * 128 * 128,
                                                         wlo + 2 * 128 * 128,
                                                         as2, ad2, hbuf, asbuf, adbuf,
                                                         N_NODES);
    aggregate_kernel<1, false><<<grid_w, 256>>>(hbuf, asbuf, adbuf, rowptr, srcs, b2,
                                                out, nullptr, nullptr);
}

// round 17
// speedup vs baseline: 1.1177x; 1.0834x over previous
#include <cuda_runtime.h>
#include <cuda_bf16.h>
#include <cuda_fp16.h>
#include <cstdint>

#define N_NODES 50000
#define N_EDGES 800000
#define TOT_E   (N_EDGES + N_NODES)   // edges + self loops
#define NEG_SLOPE 0.2f
#define FULL 0xffffffffu

#define SCAN_CHUNK 512
#define NB_SCAN ((N_NODES + SCAN_CHUNK - 1) / SCAN_CHUNK)   // 98

// tensor GEMM smem geometry: full K=128 resident, bf16 hi/lo planes
#define STRIDE 136                       // 128 + 8 pad (shorts)
#define SA_HI 0
#define SA_LO (128 * STRIDE)
#define SB_HI (2 * 128 * STRIDE)
#define SB_LO (3 * 128 * STRIDE)
#define GEMM_SM_SHORTS (4 * 128 * STRIDE)
#define GEMM_SM_BYTES  (GEMM_SM_SHORTS * 2)   // 139264

// ---------------- scratch (static device globals; no allocation) ----------------
__device__ __half         g_h16[N_NODES * 128];   // x @ W, fp16 (gather payload)
__device__ unsigned short g_xhi[N_NODES * 128];   // activations, bf16 hi plane
__device__ unsigned short g_xlo[N_NODES * 128];   // activations, bf16 lo plane
__device__ unsigned short g_whi[3 * 128 * 128];   // weights, bf16 hi planes
__device__ unsigned short g_wlo[3 * 128 * 128];   // weights, bf16 lo planes
__device__ float  g_as[N_NODES * 4];
__device__ float  g_ad[N_NODES * 4];
__device__ int    g_cnt   [N_NODES];
__device__ int    g_rowptr[N_NODES + 1];
__device__ int    g_cursor[N_NODES];
__device__ int    g_srcs  [TOT_E];
__device__ int    g_bsum  [NB_SCAN];
__device__ int    g_offs  [NB_SCAN];
__device__ int    g_is64;

// ---------------- edge_index dtype detection (1 warp) ----------------
__global__ void detect_kernel(const int* __restrict__ ei32, int* __restrict__ flag) {
    int lane = threadIdx.x;
    int nz = 0;
#pragma unroll
    for (int i = lane; i < 128; i += 32) nz |= ei32[2 * i + 1];
    int any = __any_sync(FULL, nz != 0);
    if (lane == 0) *flag = any ? 0 : 1;
}

__device__ __forceinline__ int load_idx(const void* ei, int is64, long long pos) {
    if (is64) return (int)((const long long*)ei)[pos];
    return ((const int*)ei)[pos];
}

// ---------------- CSR build ----------------
__global__ void hist_kernel(const void* __restrict__ ei, const int* __restrict__ flag,
                            int* __restrict__ cnt) {
    int i = blockIdx.x * blockDim.x + threadIdx.x;
    if (i >= TOT_E) return;
    int is64 = *flag;
    int d = (i < N_EDGES) ? load_idx(ei, is64, (long long)N_EDGES + i) : (i - N_EDGES);
    atomicAdd(&cnt[d], 1);
}

__global__ __launch_bounds__(256) void block_reduce_kernel(const int* __restrict__ cnt,
                                                           int* __restrict__ bsum) {
    int b = blockIdx.x, tid = threadIdx.x;
    int i0 = b * SCAN_CHUNK + tid * 2;
    int v = 0;
    if (i0 < N_NODES)     v += cnt[i0];
    if (i0 + 1 < N_NODES) v += cnt[i0 + 1];
#pragma unroll
    for (int off = 16; off; off >>= 1) v += __shfl_xor_sync(FULL, v, off);
    __shared__ int ws[8];
    int lane = tid & 31, wid = tid >> 5;
    if (lane == 0) ws[wid] = v;
    __syncthreads();
    if (tid == 0) {
        int s = 0;
#pragma unroll
        for (int w = 0; w < 8; w++) s += ws[w];
        bsum[b] = s;
    }
}

__global__ void scan_partials_kernel(const int* __restrict__ bsum,
                                     int* __restrict__ offs, int* __restrict__ rowptr) {
    __shared__ int sh[128];
    int tid = threadIdx.x;
    int v = (tid < NB_SCAN) ? bsum[tid] : 0;
    sh[tid] = v;
    __syncthreads();
#pragma unroll
    for (int off = 1; off < 128; off <<= 1) {
        int y = (tid >= off) ? sh[tid - off] : 0;
        __syncthreads();
        sh[tid] += y;
        __syncthreads();
    }
    if (tid < NB_SCAN) offs[tid] = sh[tid] - v;
    if (tid == 127) rowptr[N_NODES] = sh[127];
}

__global__ __launch_bounds__(256) void chunk_scan_kernel(const int* __restrict__ cnt,
                                                         const int* __restrict__ offs,
                                                         int* __restrict__ rowptr,
                                                         int* __restrict__ cursor) {
    int b = blockIdx.x, tid = threadIdx.x;
    int lane = tid & 31, wid = tid >> 5;
    int i0 = b * SCAN_CHUNK + tid * 2;
    int v0 = (i0 < N_NODES) ? cnt[i0] : 0;
    int v1 = (i0 + 1 < N_NODES) ? cnt[i0 + 1] : 0;
    int t = v0 + v1;
    int x = t;
#pragma unroll
    for (int off = 1; off < 32; off <<= 1) {
        int y = __shfl_up_sync(FULL, x, off);
        if (lane >= off) x += y;
    }
    __shared__ int ws[8], wpre[8];
    if (lane == 31) ws[wid] = x;
    __syncthreads();
    if (tid == 0) {
        int run = 0;
#pragma unroll
        for (int w = 0; w < 8; w++) { wpre[w] = run; run += ws[w]; }
    }
    __syncthreads();
    int excl = x - t + wpre[wid] + offs[b];
    if (i0 < N_NODES)     { rowptr[i0] = excl;          cursor[i0] = excl; }
    if (i0 + 1 < N_NODES) { rowptr[i0 + 1] = excl + v0; cursor[i0 + 1] = excl + v0; }
}

__global__ void scatter_kernel(const void* __restrict__ ei, const int* __restrict__ flag,
                               int* __restrict__ cursor, int* __restrict__ srcs) {
    int i = blockIdx.x * blockDim.x + threadIdx.x;
    if (i >= TOT_E) return;
    int is64 = *flag;
    int s, d;
    if (i < N_EDGES) {
        s = load_idx(ei, is64, i);
        d = load_idx(ei, is64, (long long)N_EDGES + i);
    } else { s = i - N_EDGES; d = s; }
    int pos = atomicAdd(&cursor[d], 1);
    srcs[pos] = s;
}

// ---------------- tensor-core / async helpers ----------------
__device__ __forceinline__ uint32_t smem_u32(const void* p) {
    return (uint32_t)__cvta_generic_to_shared(p);
}
__device__ __forceinline__ void cp16(uint32_t dst, const void* src, int szbytes) {
    asm volatile("cp.async.cg.shared.global [%0], [%1], 16, %2;"
        :: "r"(dst), "l"(src), "r"(szbytes));
}
__device__ __forceinline__ void ldm_x4(uint32_t* r, uint32_t addr) {
    asm volatile("ldmatrix.sync.aligned.m8n8.x4.shared.b16 {%0,%1,%2,%3}, [%4];"
        : "=r"(r[0]), "=r"(r[1]), "=r"(r[2]), "=r"(r[3]) : "r"(addr));
}
__device__ __forceinline__ void ldm_x2t(uint32_t* r, uint32_t addr) {
    asm volatile("ldmatrix.sync.aligned.m8n8.x2.trans.shared.b16 {%0,%1}, [%2];"
        : "=r"(r[0]), "=r"(r[1]) : "r"(addr));
}
__device__ __forceinline__ void mma_bf16(float* c, const uint32_t* a, const uint32_t* b) {
    asm volatile("mma.sync.aligned.m16n8k16.row.col.f32.bf16.bf16.f32 "
        "{%0,%1,%2,%3}, {%4,%5,%6,%7}, {%8,%9}, {%0,%1,%2,%3};"
        : "+f"(c[0]), "+f"(c[1]), "+f"(c[2]), "+f"(c[3])
        : "r"(a[0]), "r"(a[1]), "r"(a[2]), "r"(a[3]), "r"(b[0]), "r"(b[1]));
}
__device__ __forceinline__ void split2(float a, float b, uint32_t& hi, uint32_t& lo) {
    __nv_bfloat16 ah = __float2bfloat16_rn(a);
    __nv_bfloat16 bh = __float2bfloat16_rn(b);
    __nv_bfloat16 al = __float2bfloat16_rn(a - __bfloat162float(ah));
    __nv_bfloat16 bl = __float2bfloat16_rn(b - __bfloat162float(bh));
    hi = ((uint32_t)__bfloat16_as_ushort(bh) << 16) | (uint32_t)__bfloat16_as_ushort(ah);
    lo = ((uint32_t)__bfloat16_as_ushort(bl) << 16) | (uint32_t)__bfloat16_as_ushort(al);
}

// ---------------- fused fp32 -> bf16 hi/lo split for x + all 3 weights --------
#define NX4 (N_NODES * 128 / 4)
#define NW4 (128 * 128 / 4)
__global__ void split_all_kernel(const float* __restrict__ x,
                                 const float* __restrict__ W0,
                                 const float* __restrict__ W1,
                                 const float* __restrict__ W2,
                                 unsigned short* __restrict__ xhi,
                                 unsigned short* __restrict__ xlo,
                                 unsigned short* __restrict__ whi,
                                 unsigned short* __restrict__ wlo) {
    int i = blockIdx.x * blockDim.x + threadIdx.x;
    const float* src;
    unsigned short *dh, *dl;
    int idx;
    if (i < NX4) {
        src = x; dh = xhi; dl = xlo; idx = i;
    } else {
        int j = i - NX4;
        if (j >= 3 * NW4) return;
        int wsel = j / NW4;
        idx = j - wsel * NW4;
        src = (wsel == 0) ? W0 : (wsel == 1) ? W1 : W2;
        dh = whi + wsel * 128 * 128;
        dl = wlo + wsel * 128 * 128;
    }
    float4 v = ((const float4*)src)[idx];
    uint32_t h0, l0, h1, l1;
    split2(v.x, v.y, h0, l0);
    split2(v.z, v.w, h1, l1);
    ((uint2*)dh)[idx] = make_uint2(h0, h1);
    ((uint2*)dl)[idx] = make_uint2(l0, l1);
}

// ---------------- fused tensor GEMM + alpha (all operands pre-split) ----------
template <int H>
__global__ __launch_bounds__(512) void gemm_tc_kernel(
    const unsigned short* __restrict__ xhi, const unsigned short* __restrict__ xlo,
    const unsigned short* __restrict__ whi, const unsigned short* __restrict__ wlo,
    const float* __restrict__ a_s, const float* __restrict__ a_d,
    __half* __restrict__ out, float* __restrict__ out_s, float* __restrict__ out_d,
    int nrows) {
    extern __shared__ __align__(16) unsigned short sm[];
    unsigned short* Ahi = sm + SA_HI;
    unsigned short* Alo = sm + SA_LO;
    unsigned short* Bhi = sm + SB_HI;
    unsigned short* Blo = sm + SB_LO;

    int tid = threadIdx.x;
    int w = tid >> 5, lane = tid & 31;
    int warpRow = w >> 2, warpCol = w & 3;
    int rowBase = blockIdx.x * 128;

    // ---- front-load everything via cp.async ----
#pragma unroll
    for (int i = 0; i < 4; i++) {
        int seg = tid + i * 512;
        int r = seg >> 4, s = seg & 15;
        int grow = rowBase + r;
        int sz = (grow < nrows) ? 16 : 0;
        const unsigned short* srch = (grow < nrows) ? xhi + (size_t)grow * 128 + s * 8 : xhi;
        const unsigned short* srcl = (grow < nrows) ? xlo + (size_t)grow * 128 + s * 8 : xlo;
        int so = r * STRIDE + s * 8;
        cp16(smem_u32(Ahi + so), srch, sz);
        cp16(smem_u32(Alo + so), srcl, sz);
    }
#pragma unroll
    for (int i = 0; i < 4; i++) {
        int seg = tid + i * 512;
        int kr = seg >> 4, s = seg & 15;
        size_t go = (size_t)kr * 128 + s * 8;
        int so = kr * STRIDE + s * 8;
        cp16(smem_u32(Bhi + so), whi + go, 16);
        cp16(smem_u32(Blo + so), wlo + go, 16);
    }
    asm volatile("cp.async.commit_group;");

    float c[2][4][4];
#pragma unroll
    for (int mt = 0; mt < 2; mt++)
#pragma unroll
        for (int nt = 0; nt < 4; nt++)
#pragma unroll
            for (int f = 0; f < 4; f++) c[mt][nt][f] = 0.f;

    asm volatile("cp.async.wait_group 0;");
    __syncthreads();

    // ---- 8 uninterrupted k-steps ----
#pragma unroll
    for (int ks = 0; ks < 8; ks++) {
        int k0 = ks * 16;
        uint32_t ah[2][4], al[2][4], bh[4][2], bl[4][2];
#pragma unroll
        for (int mt = 0; mt < 2; mt++) {
            int idx = (warpRow * 32 + mt * 16 + (lane & 15)) * STRIDE
                    + k0 + ((lane >> 4) << 3);
            ldm_x4(ah[mt], smem_u32(Ahi + idx));
            ldm_x4(al[mt], smem_u32(Alo + idx));
        }
#pragma unroll
        for (int nt = 0; nt < 4; nt++) {
            int idx = (k0 + (lane & 15)) * STRIDE + warpCol * 32 + nt * 8;
            ldm_x2t(bh[nt], smem_u32(Bhi + idx));
            ldm_x2t(bl[nt], smem_u32(Blo + idx));
        }
#pragma unroll
        for (int mt = 0; mt < 2; mt++)
#pragma unroll
            for (int nt = 0; nt < 4; nt++) {
                mma_bf16(c[mt][nt], ah[mt], bh[nt]);
                mma_bf16(c[mt][nt], ah[mt], bl[nt]);
                mma_bf16(c[mt][nt], al[mt], bh[nt]);
            }
    }

    // ---- epilogue: store h as fp16 ----
#pragma unroll
    for (int mt = 0; mt < 2; mt++) {
#pragma unroll
        for (int half = 0; half < 2; half++) {
            int r = rowBase + warpRow * 32 + mt * 16 + (lane >> 2) + half * 8;
            if (r < nrows) {
#pragma unroll
                for (int nt = 0; nt < 4; nt++) {
                    int col = warpCol * 32 + nt * 8 + 2 * (lane & 3);
                    __half2 hv = __floats2half2_rn(c[mt][nt][half * 2],
                                                   c[mt][nt][half * 2 + 1]);
                    *(__half2*)(out + (size_t)r * 128 + col) = hv;
                }
            }
        }
    }

    // ---- fused alpha: per-row dots from fp32 accumulators ----
    float asv[4][2], adv[4][2];
#pragma unroll
    for (int nt = 0; nt < 4; nt++) {
        int col = warpCol * 32 + nt * 8 + 2 * (lane & 3);
        asv[nt][0] = a_s[col]; asv[nt][1] = a_s[col + 1];
        adv[nt][0] = a_d[col]; adv[nt][1] = a_d[col + 1];
    }
    if (H == 1) __syncthreads();       // protect smem overlay below
    float* redAS = (float*)sm;
    float* redAD = redAS + 4 * 128;

#pragma unroll
    for (int mt = 0; mt < 2; mt++) {
#pragma unroll
        for (int half = 0; half < 2; half++) {
            float ps = 0.f, pd = 0.f;
#pragma unroll
            for (int nt = 0; nt < 4; nt++) {
                ps += c[mt][nt][half * 2] * asv[nt][0] + c[mt][nt][half * 2 + 1] * asv[nt][1];
                pd += c[mt][nt][half * 2] * adv[nt][0] + c[mt][nt][half * 2 + 1] * adv[nt][1];
            }
            ps += __shfl_xor_sync(FULL, ps, 1); ps += __shfl_xor_sync(FULL, ps, 2);
            pd += __shfl_xor_sync(FULL, pd, 1); pd += __shfl_xor_sync(FULL, pd, 2);
            int lrow = warpRow * 32 + mt * 16 + (lane >> 2) + half * 8;
            int r = rowBase + lrow;
            if ((lane & 3) == 0) {
                if (H == 4) {
                    if (r < nrows) {
                        out_s[r * 4 + warpCol] = ps;
                        out_d[r * 4 + warpCol] = pd;
                    }
                } else {
                    redAS[warpCol * 128 + lrow] = ps;
                    redAD[warpCol * 128 + lrow] = pd;
                }
            }
        }
    }
    if (H == 1) {
        __syncthreads();
        if (tid < 128) {
            int r = rowBase + tid;
            if (r < nrows) {
                float s = redAS[tid] + redAS[128 + tid] + redAS[256 + tid] + redAS[384 + tid];
                float d = redAD[tid] + redAD[128 + tid] + redAD[256 + tid] + redAD[384 + tid];
                out_s[r] = s;
                out_d[r] = d;
            }
        }
    }
}

// ---------------- softmax + aggregation: warp per dst node (fp16 gather) ------
template <int H, bool SPLIT_OUT>
__global__ __launch_bounds__(256) void aggregate_kernel(const __half* __restrict__ h,
                                                        const float* __restrict__ as_,
                                                        const float* __restrict__ ad_,
                                                        const int* __restrict__ rowptr,
                                                        const int* __restrict__ srcs,
                                                        const float* __restrict__ bias,
                                                        float* __restrict__ outf,
                                                        unsigned short* __restrict__ ohi,
                                                        unsigned short* __restrict__ olo) {
    __shared__ float s_w[8][32 * H];
    __shared__ int   s_s[8][32];
    int n = (blockIdx.x * blockDim.x + threadIdx.x) >> 5;
    if (n >= N_NODES) return;
    int w8 = threadIdx.x >> 5;
    int lane = threadIdx.x & 31;
    int start = rowptr[n], end = rowptr[n + 1];
    int deg = end - start;
    constexpr int LPH = 32 / H;
    int head = (H == 1) ? 0 : (lane / LPH);

    float ad_all[H];
#pragma unroll
    for (int hh = 0; hh < H; hh++) ad_all[hh] = ad_[n * H + hh];

    // ---- Phase A ----
    float m[H], p[H], e_lane[H];
    int s_lane = 0;
#pragma unroll
    for (int hh = 0; hh < H; hh++) { m[hh] = -1e30f; p[hh] = 0.f; e_lane[hh] = -1e30f; }

    if (lane < deg) {
        s_lane = srcs[start + lane];
        if (H == 4) {
            float4 a4 = *(const float4*)(as_ + (size_t)s_lane * 4);
            float ea[4] = {a4.x, a4.y, a4.z, a4.w};
#pragma unroll
            for (int hh = 0; hh < 4; hh++) {
                float e = ea[hh] + ad_all[hh];
                e = (e > 0.f) ? e : NEG_SLOPE * e;
                e_lane[hh] = e; m[hh] = e; p[hh] = 1.f;
            }
        } else {
            float e = as_[s_lane] + ad_all[0];
            e = (e > 0.f) ? e : NEG_SLOPE * e;
            e_lane[0] = e; m[0] = e; p[0] = 1.f;
        }
    }
    for (int k = start + 32 + lane; k < end; k += 32) {
        int s = srcs[k];
#pragma unroll
        for (int hh = 0; hh < H; hh++) {
            float e = as_[(size_t)s * H + hh] + ad_all[hh];
            e = (e > 0.f) ? e : NEG_SLOPE * e;
            if (e > m[hh]) { p[hh] = p[hh] * __expf(m[hh] - e) + 1.f; m[hh] = e; }
            else           { p[hh] += __expf(e - m[hh]); }
        }
    }
#pragma unroll
    for (int hh = 0; hh < H; hh++) {
        float mm = m[hh], pp = p[hh];
#pragma unroll
        for (int off = 16; off > 0; off >>= 1) {
            float mo = __shfl_xor_sync(FULL, mm, off);
            float po = __shfl_xor_sync(FULL, pp, off);
            float mn = fmaxf(mm, mo);
            pp = pp * __expf(mm - mn) + po * __expf(mo - mn);
            mm = mn;
        }
        m[hh] = mm; p[hh] = pp;
    }
    {
        float wv[H];
#pragma unroll
        for (int hh = 0; hh < H; hh++)
            wv[hh] = __expf(e_lane[hh] - m[hh]) / p[hh];
        if (H == 4) {
            *(float4*)&s_w[w8][lane * 4] = make_float4(wv[0], wv[1], wv[2], wv[3]);
        } else {
            s_w[w8][lane] = wv[0];
        }
        s_s[w8][lane] = s_lane;
    }
    __syncwarp();

    // ---- Phase B: fp16 gather, fp32 accumulate ----
    float4 acc = make_float4(0.f, 0.f, 0.f, 0.f);
    int cached = (deg < 32) ? deg : 32;
#pragma unroll 4
    for (int kk = 0; kk < cached; kk++) {
        int s = s_s[w8][kk];
        float wgt = s_w[w8][kk * H + head];
        uint2 u = *(const uint2*)(h + (size_t)s * 128 + lane * 4);
        float2 f01 = __half22float2(*(__half2*)&u.x);
        float2 f23 = __half22float2(*(__half2*)&u.y);
        acc.x += f01.x * wgt; acc.y += f01.y * wgt;
        acc.z += f23.x * wgt; acc.w += f23.y * wgt;
    }
    if (deg > 32) {
        float mh, invh, adh;
        if (H == 1) { mh = m[0]; invh = 1.f / p[0]; adh = ad_all[0]; }
        else {
            mh   = (head == 0) ? m[0] : (head == 1) ? m[1] : (head == 2) ? m[2] : m[3];
            float ph = (head == 0) ? p[0] : (head == 1) ? p[1] : (head == 2) ? p[2] : p[3];
            invh = 1.f / ph;
            adh  = (head == 0) ? ad_all[0] : (head == 1) ? ad_all[1]
                 : (head == 2) ? ad_all[2] : ad_all[3];
        }
        for (int k = start + 32; k < end; k++) {
            int s = srcs[k];
            float e = as_[(size_t)s * H + head] + adh;
            e = (e > 0.f) ? e : NEG_SLOPE * e;
            float wgt = __expf(e - mh) * invh;
            uint2 u = *(const uint2*)(h + (size_t)s * 128 + lane * 4);
            float2 f01 = __half22float2(*(__half2*)&u.x);
            float2 f23 = __half22float2(*(__half2*)&u.y);
            acc.x += f01.x * wgt; acc.y += f01.y * wgt;
            acc.z += f23.x * wgt; acc.w += f23.y * wgt;
        }
    }
    float4 bv = *(const float4*)(bias + lane * 4);
    float r0 = fmaxf(acc.x + bv.x, 0.f);
    float r1 = fmaxf(acc.y + bv.y, 0.f);
    float r2 = fmaxf(acc.z + bv.z, 0.f);
    float r3 = fmaxf(acc.w + bv.w, 0.f);
    if (SPLIT_OUT) {
        uint32_t h01, l01, h23, l23;
        split2(r0, r1, h01, l01);
        split2(r2, r3, h23, l23);
        size_t off = (size_t)n * 128 + lane * 4;
        *(uint2*)(ohi + off) = make_uint2(h01, h23);
        *(uint2*)(olo + off) = make_uint2(l01, l23);
    } else {
        *(float4*)(outf + (size_t)n * 128 + lane * 4) = make_float4(r0, r1, r2, r3);
    }
}

// ---------------- launcher ----------------
extern "C" void kernel_launch(void* const* d_in, const int* in_sizes, int n_in,
                              void* d_out, int out_size) {
    const float* x  = (const float*)d_in[0];
    const void*  ei = d_in[1];
    const float* W0 = (const float*)d_in[2];
    const float* as0 = (const float*)d_in[3];
    const float* ad0 = (const float*)d_in[4];
    const float* b0 = (const float*)d_in[5];
    const float* W1 = (const float*)d_in[6];
    const float* as1 = (const float*)d_in[7];
    const float* ad1 = (const float*)d_in[8];
    const float* b1 = (const float*)d_in[9];
    const float* W2 = (const float*)d_in[10];
    const float* as2 = (const float*)d_in[11];
    const float* ad2 = (const float*)d_in[12];
    const float* b2 = (const float*)d_in[13];
    float* out = (float*)d_out;

    void* p;
    cudaGetSymbolAddress(&p, g_h16);    __half* hbuf  = (__half*)p;
    cudaGetSymbolAddress(&p, g_xhi);    unsigned short* xhi = (unsigned short*)p;
    cudaGetSymbolAddress(&p, g_xlo);    unsigned short* xlo = (unsigned short*)p;
    cudaGetSymbolAddress(&p, g_whi);    unsigned short* whi = (unsigned short*)p;
    cudaGetSymbolAddress(&p, g_wlo);    unsigned short* wlo = (unsigned short*)p;
    cudaGetSymbolAddress(&p, g_as);     float* asbuf  = (float*)p;
    cudaGetSymbolAddress(&p, g_ad);     float* adbuf  = (float*)p;
    cudaGetSymbolAddress(&p, g_cnt);    int*   cnt    = (int*)p;
    cudaGetSymbolAddress(&p, g_rowptr); int*   rowptr = (int*)p;
    cudaGetSymbolAddress(&p, g_cursor); int*   cursor = (int*)p;
    cudaGetSymbolAddress(&p, g_srcs);   int*   srcs   = (int*)p;
    cudaGetSymbolAddress(&p, g_bsum);   int*   bsum   = (int*)p;
    cudaGetSymbolAddress(&p, g_offs);   int*   offs   = (int*)p;
    cudaGetSymbolAddress(&p, g_is64);   int*   flag   = (int*)p;

    cudaFuncSetAttribute(gemm_tc_kernel<4>,
                         cudaFuncAttributeMaxDynamicSharedMemorySize, GEMM_SM_BYTES);
    cudaFuncSetAttribute(gemm_tc_kernel<1>,
                         cudaFuncAttributeMaxDynamicSharedMemorySize, GEMM_SM_BYTES);

    const int grid_e  = (TOT_E + 255) / 256;
    const int grid_w  = (N_NODES * 32 + 255) / 256;   // warp per node
    const int grid_g  = (N_NODES + 127) / 128;        // GEMM row tiles
    const int nsplit  = NX4 + 3 * NW4;

    // side stream + events for a parallel CSR branch inside graph capture
    cudaStream_t s1;
    cudaStreamCreateWithFlags(&s1, cudaStreamNonBlocking);
    cudaEvent_t evFork, evJoin;
    cudaEventCreateWithFlags(&evFork, cudaEventDisableTiming);
    cudaEventCreateWithFlags(&evJoin, cudaEventDisableTiming);

    // ---- main stream: prerequisites for both branches ----
    detect_kernel<<<1, 32>>>((const int*)ei, flag);
    cudaMemsetAsync(cnt, 0, N_NODES * sizeof(int));
    cudaEventRecord(evFork, 0);

    // ---- side branch: full CSR build ----
    cudaStreamWaitEvent(s1, evFork, 0);
    hist_kernel         <<<grid_e, 256, 0, s1>>>(ei, flag, cnt);
    block_reduce_kernel <<<NB_SCAN, 256, 0, s1>>>(cnt, bsum);
    scan_partials_kernel<<<1, 128, 0, s1>>>(bsum, offs, rowptr);
    chunk_scan_kernel   <<<NB_SCAN, 256, 0, s1>>>(cnt, offs, rowptr, cursor);
    scatter_kernel      <<<grid_e, 256, 0, s1>>>(ei, flag, cursor, srcs);
    cudaEventRecord(evJoin, s1);

    // ---- main branch: split + layer-0 GEMM (independent of CSR) ----
    split_all_kernel<<<(nsplit + 255) / 256, 256>>>(x, W0, W1, W2,
                                                    xhi, xlo, whi, wlo);
    gemm_tc_kernel<4><<<grid_g, 512, GEMM_SM_BYTES>>>(xhi, xlo, whi, wlo,
                                                      as0, ad0, hbuf, asbuf, adbuf,
                                                      N_NODES);
    // ---- join: aggregate needs both CSR and GEMM results ----
    cudaStreamWaitEvent(0, evJoin, 0);

    // layer 0 aggregate (H=4) -> split bf16 planes
    aggregate_kernel<4, true><<<grid_w, 256>>>(hbuf, asbuf, adbuf, rowptr, srcs, b0,
                                               nullptr, xhi, xlo);
    // layer 1 (H=4)
    gemm_tc_kernel<4><<<grid_g, 512, GEMM_SM_BYTES>>>(xhi, xlo,
                                                      whi + 128 * 128, wlo + 128 * 128,
                                                      as1, ad1, hbuf, asbuf, adbuf,
                                                      N_NODES);
    aggregate_kernel<4, true><<<grid_w, 256>>>(hbuf, asbuf, adbuf, rowptr, srcs, b1,
                                               nullptr, xhi, xlo);
    // layer 2 (H=1)
    gemm_tc_kernel<1><<<grid_g, 512, GEMM_SM_BYTES>>>(xhi, xlo,
                                                      whi + 2 * 128 * 128,
                                                      wlo + 2 * 128 * 128,
                                                      as2, ad2, hbuf, asbuf, adbuf,
                                                      N_NODES);
    aggregate_kernel<1, false><<<grid_w, 256>>>(hbuf, asbuf, adbuf, rowptr, srcs, b2,
                                                out, nullptr, nullptr);
}